// round 8
// baseline (speedup 1.0000x reference)
#include <cuda_runtime.h>

// Problem constants
#define BATCH      2048
#define N_OH       20
#define N_OT       23
#define NCLS       10
#define EMB        9
#define OUTC       32
#define HW         2304          // 48*48
#define VSZ        (BATCH*EMB)   // 18432
#define OSZ        (BATCH*N_OT)  // 47104
#define F4COUNT    147456        // 8*32*2304/4
#define REPS       256
#define NBLOCKS    576
#define NPREP      256           // blocks doing phase A (VSZ+OSZ = 65536 = 256*256)

// Scratch (allocation-free rule: __device__ globals)
__device__ __align__(16) float g_vflat[VSZ];
__device__ __align__(16) float g_oflat[OSZ];
__device__ unsigned g_ready;     // zero-init; reset at end of every launch
__device__ unsigned g_done;

// ---------------------------------------------------------------------------
// Single fused kernel (all 576 blocks co-resident: 48 regs x 256 thr ->
// 4 blocks/SM x 148 SMs = 592 slots, so the global barrier is safe).
//  Phase A (blocks 0..255): one prep item per thread (vflat gather-sum or
//                           oflat copy) -> single memory round-trip.
//  Phase B (all blocks):    fold the 3 linear layers for this block's <=2
//                           output channels into SMEM (hides barrier skew).
//  Phase C (all blocks):    spin until all NPREP arrivals, compute the 4KB
//                           F-slice, redistribute via SMEM, write 32
//                           reps/warp as 4KB-contiguous STG.128 bursts.
// out.flat[rep*589824 + i] = F.flat[i]  (output = F tile repeated 256x).
// ---------------------------------------------------------------------------
__global__ void __launch_bounds__(256) fused_kernel(
    const float* __restrict__ x,
    const float* __restrict__ fc_w,
    const float* __restrict__ fc_b,
    const float* __restrict__ oh_w,
    const float* __restrict__ oh_b,
    const float* __restrict__ ot_w,
    const float* __restrict__ ot_b,
    const float* __restrict__ all_w,
    const float* __restrict__ all_b,
    float4* __restrict__ out4)
{
    __shared__ float4 sF[256];
    __shared__ float sW1[2][EMB];
    __shared__ float sW2[2][N_OT];
    __shared__ float sBias[2];

    const int tid = threadIdx.x;
    const int bid = blockIdx.x;

    // ---------------- Phase A: prep, one item per thread ----------------
    if (bid < NPREP) {
        int t = bid * 256 + tid;                 // [0, 65536) = VSZ + OSZ
        if (t < VSZ) {
            // vflat[b*9+e] = fc_b[e] + sum_i fc_w[e, i*10 + idx[b,i]]
            int b = t / EMB;
            int e = t - b * EMB;
            const float* xr = x + b * (N_OH + N_OT);
            const float* wr = fc_w + e * (N_OH * NCLS);
            float acc = fc_b[e];
            #pragma unroll
            for (int i = 0; i < N_OH; i++) {
                int cls = (int)xr[i];
                acc += wr[i * NCLS + cls];
            }
            g_vflat[t] = acc;
        } else {
            int j = t - VSZ;                     // [0, OSZ)
            int b = j / N_OT;
            int c = j - b * N_OT;
            g_oflat[j] = x[b * (N_OH + N_OT) + N_OH + c];
        }
        __threadfence();
        __syncthreads();
        if (tid == 0) atomicAdd(&g_ready, 1u);
    }

    // ---------------- Phase B: per-block weight fold (prep-independent) ----
    // Block covers i4 in [bid*256, bid*256+256): one m, at most 2 oc values.
    const int i4 = bid * 256 + tid;
    const int m  = i4 / (OUTC * (HW / 4));       // 18432 per m
    const int r  = i4 - m * (OUTC * (HW / 4));
    const int oc = r / (HW / 4);
    const int hw4 = r - oc * (HW / 4);
    const int hw0 = hw4 * 4;

    const int r0  = bid * 256 - m * (OUTC * (HW / 4));
    const int ocA = r0 / (HW / 4);
    const int ocB = (r0 + 255) / (HW / 4);

    if (tid < 18) {                       // W1 fold: all_w[:, :9] @ oh_w
        int half = tid / EMB;             // 0 -> ocA, 1 -> ocB
        int e = tid - half * EMB;
        int c_oc = half ? ocB : ocA;
        const float* aw = all_w + c_oc * OUTC;
        float s = 0.f;
        #pragma unroll
        for (int o = 0; o < EMB; o++) s += aw[o] * oh_w[o * EMB + e];
        sW1[half][e] = s;
    } else if (tid >= 32 && tid < 32 + 2 * N_OT) {   // W2 fold
        int j = tid - 32;
        int half = j / N_OT;
        int c = j - half * N_OT;
        int c_oc = half ? ocB : ocA;
        const float* aw = all_w + c_oc * OUTC + EMB;
        float s = 0.f;
        #pragma unroll
        for (int o = 0; o < N_OT; o++) s += aw[o] * ot_w[o * N_OT + c];
        sW2[half][c] = s;
    } else if (tid == 96 || tid == 97) {             // folded bias
        int half = tid - 96;
        int c_oc = half ? ocB : ocA;
        const float* aw = all_w + c_oc * OUTC;
        float bsum = all_b[c_oc];
        #pragma unroll
        for (int o = 0; o < EMB; o++) bsum += aw[o] * oh_b[o];
        #pragma unroll
        for (int o = 0; o < N_OT; o++) bsum += aw[EMB + o] * ot_b[o];
        sBias[half] = bsum;
    }
    __syncthreads();                      // weights ready in SMEM

    // ---------------- Global barrier: wait for all NPREP arrivals ----------
    if (tid == 0) {
        while (*(volatile unsigned*)&g_ready < NPREP) { }
    }
    __syncthreads();

    // ---------------- Phase C: compute F slice ----------------
    const int sel = (oc == ocA) ? 0 : 1;
    float bs = sBias[sel];
    float4 acc; acc.x = bs; acc.y = bs; acc.z = bs; acc.w = bs;

    // v contribution: v_map[m,e,hw] = vflat[2304*((m+e)&7) + hw]  (9 taps)
    const float4* vf4 = (const float4*)g_vflat;
    #pragma unroll
    for (int e = 0; e < EMB; e++) {
        int row = m + e; if (row >= 8) row -= 8;
        float w = sW1[sel][e];
        float4 v = vf4[row * (HW / 4) + hw4];
        acc.x += w * v.x; acc.y += w * v.y; acc.z += w * v.z; acc.w += w * v.w;
    }

    // others contribution: o_map[m,c,hw] = oflat[(5888*m + 2304*c + hw) mod 47104]
    // max index = 94204 < 2*OSZ -> one conditional subtract; offsets are
    // multiples of 4 so float4 never straddles the wrap.
    const float4* of4 = (const float4*)g_oflat;
    int baseo = m * 5888 + hw0;
    #pragma unroll
    for (int c = 0; c < N_OT; c++) {
        int idx = baseo + c * HW;
        if (idx >= OSZ) idx -= OSZ;
        float w = sW2[sel][c];
        float4 v = of4[idx >> 2];
        acc.x += w * v.x; acc.y += w * v.y; acc.z += w * v.z; acc.w += w * v.w;
    }

    sF[tid] = acc;
    __syncthreads();

    // Redistribute: lane l of each warp holds the full 4KB slice (8 float4s,
    // bytes [j*512 + l*16)). Each warp writes 32 whole reps; per rep 8
    // back-to-back STG.128 covering 4KB contiguous.
    int w = tid >> 5;
    int lane = tid & 31;
    float4 rv[8];
    #pragma unroll
    for (int j = 0; j < 8; j++) rv[j] = sF[j * 32 + lane];

    float4* base = out4 + (size_t)bid * 256 + lane;
    #pragma unroll 4
    for (int k = 0; k < 32; k++) {
        int rep = w * 32 + k;
        float4* p = base + (size_t)rep * F4COUNT;
        #pragma unroll
        for (int j = 0; j < 8; j++) {
            __stcs(p + j * 32, rv[j]);
        }
    }

    // ---------------- Replay-safe reset ----------------
    if (tid == 0) {
        unsigned d = atomicAdd(&g_done, 1u);
        if (d == NBLOCKS - 1) {
            atomicExch(&g_ready, 0u);
            atomicExch(&g_done, 0u);
        }
    }
}

// ---------------------------------------------------------------------------
extern "C" void kernel_launch(void* const* d_in, const int* in_sizes, int n_in,
                              void* d_out, int out_size)
{
    const float* x     = (const float*)d_in[0];
    const float* fc_w  = (const float*)d_in[1];
    const float* fc_b  = (const float*)d_in[2];
    const float* oh_w  = (const float*)d_in[3];
    const float* oh_b  = (const float*)d_in[4];
    const float* ot_w  = (const float*)d_in[5];
    const float* ot_b  = (const float*)d_in[6];
    const float* all_w = (const float*)d_in[7];
    const float* all_b = (const float*)d_in[8];

    fused_kernel<<<NBLOCKS, 256>>>(x, fc_w, fc_b, oh_w, oh_b,
                                   ot_w, ot_b, all_w, all_b,
                                   (float4*)d_out);
}

// round 9
// speedup vs baseline: 1.0069x; 1.0069x over previous
#include <cuda_runtime.h>

// Problem constants
#define BATCH      2048
#define N_OH       20
#define N_OT       23
#define NCLS       10
#define EMB        9
#define OUTC       32
#define HW         2304          // 48*48
#define VSZ        (BATCH*EMB)   // 18432
#define OSZ        (BATCH*N_OT)  // 47104
#define F4COUNT    147456        // 8*32*2304/4
#define REPS       256
#define NBLOCKS    576
#define NPREP_O    184           // blocks 0..183 copy oflat   (184*256 = 47104)
#define NPREP_V    72            // blocks 184..255 build vflat (72*256 = 18432)

// Scratch (allocation-free rule: __device__ globals)
__device__ __align__(16) float g_vflat[VSZ];
__device__ __align__(16) float g_oflat[OSZ];
__device__ unsigned g_ready_o;   // zero-init; reset at end of every launch
__device__ unsigned g_ready_v;
__device__ unsigned g_done;

// ---------------------------------------------------------------------------
// Single fused kernel (all 576 blocks co-resident: 48 regs x 256 thr ->
// 4 blocks/SM x 148 SMs = 592 slots, so the global barriers are safe).
//  Phase A  (blocks   0..183): copy oflat, 1 item/thread (1 round-trip) -> o-flag
//           (blocks 184..255): build vflat gather-sums (2 round-trips)  -> v-flag
//  Phase B  (all blocks): fold the 3 linear layers into SMEM (no deps).
//  Phase C  (all blocks): wait o-flag -> 23-tap o-contribution (hides the
//           v-flag wait) -> wait v-flag -> 9 v-taps -> SMEM redistribute ->
//           32 reps/warp as 4KB-contiguous STG.128 bursts.
// out.flat[rep*589824 + i] = F.flat[i]  (output = F tile repeated 256x).
// ---------------------------------------------------------------------------
__global__ void __launch_bounds__(256) fused_kernel(
    const float* __restrict__ x,
    const float* __restrict__ fc_w,
    const float* __restrict__ fc_b,
    const float* __restrict__ oh_w,
    const float* __restrict__ oh_b,
    const float* __restrict__ ot_w,
    const float* __restrict__ ot_b,
    const float* __restrict__ all_w,
    const float* __restrict__ all_b,
    float4* __restrict__ out4)
{
    __shared__ float4 sF[256];
    __shared__ float sW1[2][EMB];
    __shared__ float sW2[2][N_OT];
    __shared__ float sBias[2];

    const int tid = threadIdx.x;
    const int bid = blockIdx.x;

    // ---------------- Phase A: prep producers ----------------
    if (bid < NPREP_O) {
        // oflat copy: 1 item per thread, single round-trip
        int j = bid * 256 + tid;                 // [0, OSZ)
        int b = j / N_OT;
        int c = j - b * N_OT;
        g_oflat[j] = x[b * (N_OH + N_OT) + N_OH + c];
        __threadfence();
        __syncthreads();
        if (tid == 0) atomicAdd(&g_ready_o, 1u);
    } else if (bid < NPREP_O + NPREP_V) {
        // vflat[b*9+e] = fc_b[e] + sum_i fc_w[e, i*10 + idx[b,i]]
        int t = (bid - NPREP_O) * 256 + tid;     // [0, VSZ)
        int b = t / EMB;
        int e = t - b * EMB;
        const float* xr = x + b * (N_OH + N_OT);
        const float* wr = fc_w + e * (N_OH * NCLS);
        float acc = fc_b[e];
        #pragma unroll
        for (int i = 0; i < N_OH; i++) {
            int cls = (int)xr[i];
            acc += wr[i * NCLS + cls];
        }
        g_vflat[t] = acc;
        __threadfence();
        __syncthreads();
        if (tid == 0) atomicAdd(&g_ready_v, 1u);
    }

    // ---------------- Phase B: per-block weight fold (prep-independent) ----
    // Block covers i4 in [bid*256, bid*256+256): one m, at most 2 oc values.
    const int i4 = bid * 256 + tid;
    const int m  = i4 / (OUTC * (HW / 4));       // 18432 per m
    const int r  = i4 - m * (OUTC * (HW / 4));
    const int oc = r / (HW / 4);
    const int hw4 = r - oc * (HW / 4);
    const int hw0 = hw4 * 4;

    const int r0  = bid * 256 - m * (OUTC * (HW / 4));
    const int ocA = r0 / (HW / 4);
    const int ocB = (r0 + 255) / (HW / 4);

    if (tid < 18) {                       // W1 fold: all_w[:, :9] @ oh_w
        int half = tid / EMB;             // 0 -> ocA, 1 -> ocB
        int e = tid - half * EMB;
        int c_oc = half ? ocB : ocA;
        const float* aw = all_w + c_oc * OUTC;
        float s = 0.f;
        #pragma unroll
        for (int o = 0; o < EMB; o++) s += aw[o] * oh_w[o * EMB + e];
        sW1[half][e] = s;
    } else if (tid >= 32 && tid < 32 + 2 * N_OT) {   // W2 fold
        int j = tid - 32;
        int half = j / N_OT;
        int c = j - half * N_OT;
        int c_oc = half ? ocB : ocA;
        const float* aw = all_w + c_oc * OUTC + EMB;
        float s = 0.f;
        #pragma unroll
        for (int o = 0; o < N_OT; o++) s += aw[o] * ot_w[o * N_OT + c];
        sW2[half][c] = s;
    } else if (tid == 96 || tid == 97) {             // folded bias
        int half = tid - 96;
        int c_oc = half ? ocB : ocA;
        const float* aw = all_w + c_oc * OUTC;
        float bsum = all_b[c_oc];
        #pragma unroll
        for (int o = 0; o < EMB; o++) bsum += aw[o] * oh_b[o];
        #pragma unroll
        for (int o = 0; o < N_OT; o++) bsum += aw[EMB + o] * ot_b[o];
        sBias[half] = bsum;
    }
    __syncthreads();                      // weights ready in SMEM

    // ---------------- Wait for oflat (early flag) ----------------
    if (tid == 0) {
        while (*(volatile unsigned*)&g_ready_o < NPREP_O) { }
    }
    __syncthreads();

    // ---------------- o-contribution first (hides the vflat wait) ---------
    const int sel = (oc == ocA) ? 0 : 1;
    float bs = sBias[sel];
    float4 acc; acc.x = bs; acc.y = bs; acc.z = bs; acc.w = bs;

    // o_map[m,c,hw] = oflat[(5888*m + 2304*c + hw) mod 47104]
    // max index = 94204 < 2*OSZ -> one conditional subtract; offsets are
    // multiples of 4 so float4 never straddles the wrap.
    const float4* of4 = (const float4*)g_oflat;
    int baseo = m * 5888 + hw0;
    #pragma unroll
    for (int c = 0; c < N_OT; c++) {
        int idx = baseo + c * HW;
        if (idx >= OSZ) idx -= OSZ;
        float w = sW2[sel][c];
        float4 v = of4[idx >> 2];
        acc.x += w * v.x; acc.y += w * v.y; acc.z += w * v.z; acc.w += w * v.w;
    }

    // ---------------- Wait for vflat (late flag; likely already set) ------
    if (tid == 0) {
        while (*(volatile unsigned*)&g_ready_v < NPREP_V) { }
    }
    __syncthreads();

    // v contribution: v_map[m,e,hw] = vflat[2304*((m+e)&7) + hw]  (9 taps)
    const float4* vf4 = (const float4*)g_vflat;
    #pragma unroll
    for (int e = 0; e < EMB; e++) {
        int row = m + e; if (row >= 8) row -= 8;
        float w = sW1[sel][e];
        float4 v = vf4[row * (HW / 4) + hw4];
        acc.x += w * v.x; acc.y += w * v.y; acc.z += w * v.z; acc.w += w * v.w;
    }

    sF[tid] = acc;
    __syncthreads();

    // Redistribute: lane l of each warp holds the full 4KB slice (8 float4s,
    // bytes [j*512 + l*16)). Each warp writes 32 whole reps; per rep 8
    // back-to-back STG.128 covering 4KB contiguous.
    int w = tid >> 5;
    int lane = tid & 31;
    float4 rv[8];
    #pragma unroll
    for (int j = 0; j < 8; j++) rv[j] = sF[j * 32 + lane];

    float4* base = out4 + (size_t)bid * 256 + lane;
    #pragma unroll 4
    for (int k = 0; k < 32; k++) {
        int rep = w * 32 + k;
        float4* p = base + (size_t)rep * F4COUNT;
        #pragma unroll
        for (int j = 0; j < 8; j++) {
            __stcs(p + j * 32, rv[j]);
        }
    }

    // ---------------- Replay-safe reset ----------------
    if (tid == 0) {
        unsigned d = atomicAdd(&g_done, 1u);
        if (d == NBLOCKS - 1) {
            atomicExch(&g_ready_o, 0u);
            atomicExch(&g_ready_v, 0u);
            atomicExch(&g_done, 0u);
        }
    }
}

// ---------------------------------------------------------------------------
extern "C" void kernel_launch(void* const* d_in, const int* in_sizes, int n_in,
                              void* d_out, int out_size)
{
    const float* x     = (const float*)d_in[0];
    const float* fc_w  = (const float*)d_in[1];
    const float* fc_b  = (const float*)d_in[2];
    const float* oh_w  = (const float*)d_in[3];
    const float* oh_b  = (const float*)d_in[4];
    const float* ot_w  = (const float*)d_in[5];
    const float* ot_b  = (const float*)d_in[6];
    const float* all_w = (const float*)d_in[7];
    const float* all_b = (const float*)d_in[8];

    fused_kernel<<<NBLOCKS, 256>>>(x, fc_w, fc_b, oh_w, oh_b,
                                   ot_w, ot_b, all_w, all_b,
                                   (float4*)d_out);
}